// round 1
// baseline (speedup 1.0000x reference)
#include <cuda_runtime.h>

// Problem constants (fixed by the reference)
#define NV      100000
#define NE      1600000
#define GRIDW   128
#define G2      (GRIDW*GRIDW)
#define G3      (GRIDW*GRIDW*GRIDW)
#define NBLK1   ((NV + 1023) / 1024)   // 98 scan blocks

// ---------------- device scratch (no allocs allowed) ----------------
__device__ int   g_deg[NV];
__device__ int   g_off[NV];
__device__ int   g_cursor[NV];
__device__ int   g_csr[NE];
__device__ float g_invdeg[NV];
__device__ int   g_bsum[128];
__device__ int   g_bbase[128];

__device__ float g_X0[NV * 32];   // padded 19->32 (coords + 16 sampled + zeros)
__device__ float g_X1[NV * 32];
__device__ float g_X2[NV * 64];
__device__ float g_X3[NV * 64];

// ---------------- CSR build ----------------
__global__ void k_zero_deg() {
    int i = blockIdx.x * blockDim.x + threadIdx.x;
    if (i < NV) g_deg[i] = 0;
}

__global__ void k_deg(const int* __restrict__ dst) {
    int e = blockIdx.x * blockDim.x + threadIdx.x;
    if (e < NE) atomicAdd(&g_deg[dst[e]], 1);
}

__global__ void k_scan1() {
    __shared__ int s[1024];
    int t = threadIdx.x;
    int i = blockIdx.x * 1024 + t;
    int v = (i < NV) ? g_deg[i] : 0;
    s[t] = v;
    __syncthreads();
    for (int d = 1; d < 1024; d <<= 1) {
        int a = (t >= d) ? s[t - d] : 0;
        __syncthreads();
        s[t] += a;
        __syncthreads();
    }
    if (i < NV) g_off[i] = s[t] - v;          // exclusive within block
    if (t == 1023) g_bsum[blockIdx.x] = s[1023];
}

__global__ void k_scan2() {
    __shared__ int s[128];
    int t = threadIdx.x;
    int v = (t < NBLK1) ? g_bsum[t] : 0;
    s[t] = v;
    __syncthreads();
    for (int d = 1; d < 128; d <<= 1) {
        int a = (t >= d) ? s[t - d] : 0;
        __syncthreads();
        s[t] += a;
        __syncthreads();
    }
    g_bbase[t] = s[t] - v;                    // exclusive block bases
}

__global__ void k_scan3() {
    int i = blockIdx.x * blockDim.x + threadIdx.x;
    if (i < NV) {
        int o = g_off[i] + g_bbase[i >> 10];
        g_off[i] = o;
        g_cursor[i] = o;
        int d = g_deg[i];
        g_invdeg[i] = 1.0f / fmaxf((float)d, 1.0f);
    }
}

__global__ void k_scatter(const int* __restrict__ src, const int* __restrict__ dst) {
    int e = blockIdx.x * blockDim.x + threadIdx.x;
    if (e < NE) {
        int p = atomicAdd(&g_cursor[dst[e]], 1);
        g_csr[p] = src[e];
    }
}

// ---------------- trilinear sampling + feature assembly ----------------
__global__ void k_sample(const float* __restrict__ img, const float* __restrict__ verts) {
    int tid = blockIdx.x * blockDim.x + threadIdx.x;
    if (tid >= NV * 16) return;
    int v = tid >> 4;
    int c = tid & 15;

    float px = verts[v * 3 + 0];
    float py = verts[v * 3 + 1];
    float pz = verts[v * 3 + 2];

    if (c < 3) {
        float coord = (c == 0) ? px : (c == 1 ? py : pz);
        g_X0[v * 32 + c] = coord * (1.0f / (float)GRIDW);
    }
    if (c < 13) g_X0[v * 32 + 19 + c] = 0.0f;

    float cx = fminf(fmaxf(px, 0.0f), 127.0f);
    float cy = fminf(fmaxf(py, 0.0f), 127.0f);
    float cz = fminf(fmaxf(pz, 0.0f), 127.0f);
    float fx0 = floorf(cx), fy0 = floorf(cy), fz0 = floorf(cz);
    int x0 = (int)fx0, y0 = (int)fy0, z0 = (int)fz0;
    int x1 = min(x0 + 1, 127), y1 = min(y0 + 1, 127), z1 = min(z0 + 1, 127);
    float wx = cx - fx0, wy = cy - fy0, wz = cz - fz0;

    const float* ch = img + (size_t)c * G3;
    int b00 = (x0 << 14) + (y0 << 7);
    int b01 = (x0 << 14) + (y1 << 7);
    int b10 = (x1 << 14) + (y0 << 7);
    int b11 = (x1 << 14) + (y1 << 7);

    float v000 = ch[b00 + z0], v001 = ch[b00 + z1];
    float v010 = ch[b01 + z0], v011 = ch[b01 + z1];
    float v100 = ch[b10 + z0], v101 = ch[b10 + z1];
    float v110 = ch[b11 + z0], v111 = ch[b11 + z1];

    float c00 = v000 * (1.0f - wz) + v001 * wz;
    float c01 = v010 * (1.0f - wz) + v011 * wz;
    float c10 = v100 * (1.0f - wz) + v101 * wz;
    float c11 = v110 * (1.0f - wz) + v111 * wz;

    float val = (c00 * (1.0f - wy) + c01 * wy) * (1.0f - wx)
              + (c10 * (1.0f - wy) + c11 * wy) * wx;

    g_X0[v * 32 + 3 + c] = val;
}

// ---------------- fused edge_conv layer (aggregate + dual-GEMM + act) ----------------
// One warp per vertex. Weights + bias cached in smem (zero-padded rows for DIN<DINP).
template<int DINP, int DOUT, bool RELU, bool FINAL>
__global__ void __launch_bounds__(256)
k_layer(const float* __restrict__ X, float* __restrict__ Y,
        const float* __restrict__ Wsg, const float* __restrict__ Wng,
        const float* __restrict__ Bg, int din_real,
        const float* __restrict__ verts)
{
    constexpr int WARPS = 8;
    constexpr int NR = DINP / 32;
    constexpr int NO = (DOUT + 31) / 32;

    __shared__ float Ws[DINP * DOUT];
    __shared__ float Wn[DINP * DOUT];
    __shared__ float Bs[DOUT];
    __shared__ float xs[WARPS][DINP];
    __shared__ float ns[WARPS][DINP];

    int t = threadIdx.x;
    int nvalid = din_real * DOUT;
    for (int i = t; i < DINP * DOUT; i += 256) {
        Ws[i] = (i < nvalid) ? Wsg[i] : 0.0f;
        Wn[i] = (i < nvalid) ? Wng[i] : 0.0f;
    }
    if (t < DOUT) Bs[t] = Bg[t];
    __syncthreads();

    int warp = t >> 5;
    int lane = t & 31;

    for (int v = blockIdx.x * WARPS + warp; v < NV; v += gridDim.x * WARPS) {
        float xv[NR], nb[NR];
#pragma unroll
        for (int r = 0; r < NR; r++) {
            xv[r] = X[v * DINP + r * 32 + lane];
            nb[r] = 0.0f;
        }
        int o = g_off[v];
        int d = g_deg[v];
        for (int k = 0; k < d; k++) {
            int s = g_csr[o + k];
#pragma unroll
            for (int r = 0; r < NR; r++)
                nb[r] += X[s * DINP + r * 32 + lane];
        }
        float idg = g_invdeg[v];
#pragma unroll
        for (int r = 0; r < NR; r++) {
            xs[warp][r * 32 + lane] = xv[r];
            ns[warp][r * 32 + lane] = nb[r] * idg;
        }
        __syncwarp();

        float acc[NO];
#pragma unroll
        for (int q = 0; q < NO; q++) {
            int j = q * 32 + lane;
            acc[q] = (j < DOUT) ? Bs[j] : 0.0f;
        }
#pragma unroll 8
        for (int i = 0; i < DINP; i++) {
            float xi = xs[warp][i];
            float ni = ns[warp][i];
#pragma unroll
            for (int q = 0; q < NO; q++) {
                int j = q * 32 + lane;
                if (j < DOUT) {
                    acc[q] = fmaf(xi, Ws[i * DOUT + j], acc[q]);
                    acc[q] = fmaf(ni, Wn[i * DOUT + j], acc[q]);
                }
            }
        }

        if (FINAL) {
            if (lane < 3)
                Y[v * 3 + lane] = verts[v * 3 + lane] + 0.1f * acc[0];
        } else {
#pragma unroll
            for (int q = 0; q < NO; q++) {
                int j = q * 32 + lane;
                if (j < DOUT) {
                    float y = acc[q];
                    if (RELU) y = fmaxf(y, 0.3f * y);   // leaky_relu(0.3)
                    Y[v * DOUT + j] = y;
                }
            }
        }
        __syncwarp();   // protect xs/ns before next loop trip
    }
}

// ---------------- launch ----------------
extern "C" void kernel_launch(void* const* d_in, const int* in_sizes, int n_in,
                              void* d_out, int out_size)
{
    const float* img   = (const float*)d_in[0];
    const float* verts = (const float*)d_in[1];
    const int*   esrc  = (const int*)d_in[2];
    const int*   edst  = (const int*)d_in[3];
    const float* ws0 = (const float*)d_in[4];
    const float* wn0 = (const float*)d_in[5];
    const float* b0  = (const float*)d_in[6];
    const float* ws1 = (const float*)d_in[7];
    const float* wn1 = (const float*)d_in[8];
    const float* b1  = (const float*)d_in[9];
    const float* ws2 = (const float*)d_in[10];
    const float* wn2 = (const float*)d_in[11];
    const float* b2  = (const float*)d_in[12];
    const float* ws3 = (const float*)d_in[13];
    const float* wn3 = (const float*)d_in[14];
    const float* b3  = (const float*)d_in[15];
    float* out = (float*)d_out;

    float *x0p, *x1p, *x2p, *x3p;
    cudaGetSymbolAddress((void**)&x0p, g_X0);
    cudaGetSymbolAddress((void**)&x1p, g_X1);
    cudaGetSymbolAddress((void**)&x2p, g_X2);
    cudaGetSymbolAddress((void**)&x3p, g_X3);

    const int TB = 256;
    const int GV = (NV + TB - 1) / TB;       // vertex-sized grids
    const int GE = (NE + TB - 1) / TB;       // edge-sized grids
    const int GL = 1184;                     // layer kernels (stride loop)

    // CSR build
    k_zero_deg<<<GV, TB>>>();
    k_deg<<<GE, TB>>>(edst);
    k_scan1<<<NBLK1, 1024>>>();
    k_scan2<<<1, 128>>>();
    k_scan3<<<GV, TB>>>();
    k_scatter<<<GE, TB>>>(esrc, edst);

    // features
    k_sample<<<(NV * 16 + TB - 1) / TB, TB>>>(img, verts);

    // layers: 19(->32pad)->32 -> 64 -> 64 -> 3
    k_layer<32, 32, true,  false><<<GL, TB>>>(x0p, x1p, ws0, wn0, b0, 19, nullptr);
    k_layer<32, 64, true,  false><<<GL, TB>>>(x1p, x2p, ws1, wn1, b1, 32, nullptr);
    k_layer<64, 64, true,  false><<<GL, TB>>>(x2p, x3p, ws2, wn2, b2, 64, nullptr);
    k_layer<64, 3,  false, true ><<<GL, TB>>>(x3p, out, ws3, wn3, b3, 64, verts);
}

// round 2
// speedup vs baseline: 1.1423x; 1.1423x over previous
#include <cuda_runtime.h>

typedef unsigned long long ull;

// Problem constants (fixed by the reference)
#define NV      100000
#define NE      1600000
#define GRIDW   128
#define G3      (GRIDW*GRIDW*GRIDW)
#define NBLK1   ((NV + 1023) / 1024)   // 98 scan blocks

// ---------------- device scratch (no allocs allowed) ----------------
__device__ int   g_deg[NV];
__device__ int   g_off[NV];
__device__ int   g_cursor[NV];
__device__ int   g_csr[NE];
__device__ float g_invdeg[NV];
__device__ int   g_bsum[128];
__device__ int   g_bbase[128];

__device__ float g_X0[NV * 32];   // padded 19->32 (coords + 16 sampled + zeros)
__device__ float g_X1[NV * 32];
__device__ float g_X2[NV * 64];
__device__ float g_X3[NV * 64];

// ---------------- f32x2 helpers ----------------
__device__ __forceinline__ ull pack2(float lo, float hi) {
    ull r; asm("mov.b64 %0, {%1,%2};" : "=l"(r) : "f"(lo), "f"(hi)); return r;
}
__device__ __forceinline__ float2 unpack2(ull v) {
    float2 f; asm("mov.b64 {%0,%1}, %2;" : "=f"(f.x), "=f"(f.y) : "l"(v)); return f;
}
__device__ __forceinline__ ull fma2(ull a, ull b, ull c) {
    ull d; asm("fma.rn.f32x2 %0, %1, %2, %3;" : "=l"(d) : "l"(a), "l"(b), "l"(c)); return d;
}

// ---------------- CSR build ----------------
__global__ void k_zero_deg() {
    int i = blockIdx.x * blockDim.x + threadIdx.x;
    if (i < NV) g_deg[i] = 0;
}

__global__ void k_deg(const int* __restrict__ dst) {
    int e = blockIdx.x * blockDim.x + threadIdx.x;
    if (e < NE) atomicAdd(&g_deg[dst[e]], 1);
}

__global__ void k_scan1() {
    __shared__ int s[1024];
    int t = threadIdx.x;
    int i = blockIdx.x * 1024 + t;
    int v = (i < NV) ? g_deg[i] : 0;
    s[t] = v;
    __syncthreads();
    for (int d = 1; d < 1024; d <<= 1) {
        int a = (t >= d) ? s[t - d] : 0;
        __syncthreads();
        s[t] += a;
        __syncthreads();
    }
    if (i < NV) g_off[i] = s[t] - v;          // exclusive within block
    if (t == 1023) g_bsum[blockIdx.x] = s[1023];
}

__global__ void k_scan2() {
    __shared__ int s[128];
    int t = threadIdx.x;
    int v = (t < NBLK1) ? g_bsum[t] : 0;
    s[t] = v;
    __syncthreads();
    for (int d = 1; d < 128; d <<= 1) {
        int a = (t >= d) ? s[t - d] : 0;
        __syncthreads();
        s[t] += a;
        __syncthreads();
    }
    g_bbase[t] = s[t] - v;                    // exclusive block bases
}

__global__ void k_scan3() {
    int i = blockIdx.x * blockDim.x + threadIdx.x;
    if (i < NV) {
        int o = g_off[i] + g_bbase[i >> 10];
        g_off[i] = o;
        g_cursor[i] = o;
        int d = g_deg[i];
        g_invdeg[i] = 1.0f / fmaxf((float)d, 1.0f);
    }
}

__global__ void k_scatter(const int* __restrict__ src, const int* __restrict__ dst) {
    int e = blockIdx.x * blockDim.x + threadIdx.x;
    if (e < NE) {
        int p = atomicAdd(&g_cursor[dst[e]], 1);
        g_csr[p] = src[e];
    }
}

// ---------------- trilinear sampling + feature assembly ----------------
__global__ void k_sample(const float* __restrict__ img, const float* __restrict__ verts) {
    int tid = blockIdx.x * blockDim.x + threadIdx.x;
    if (tid >= NV * 16) return;
    int v = tid >> 4;
    int c = tid & 15;

    float px = verts[v * 3 + 0];
    float py = verts[v * 3 + 1];
    float pz = verts[v * 3 + 2];

    if (c < 3) {
        float coord = (c == 0) ? px : (c == 1 ? py : pz);
        g_X0[v * 32 + c] = coord * (1.0f / (float)GRIDW);
    }
    if (c < 13) g_X0[v * 32 + 19 + c] = 0.0f;

    float cx = fminf(fmaxf(px, 0.0f), 127.0f);
    float cy = fminf(fmaxf(py, 0.0f), 127.0f);
    float cz = fminf(fmaxf(pz, 0.0f), 127.0f);
    float fx0 = floorf(cx), fy0 = floorf(cy), fz0 = floorf(cz);
    int x0 = (int)fx0, y0 = (int)fy0, z0 = (int)fz0;
    int x1 = min(x0 + 1, 127), y1 = min(y0 + 1, 127), z1 = min(z0 + 1, 127);
    float wx = cx - fx0, wy = cy - fy0, wz = cz - fz0;

    const float* ch = img + (size_t)c * G3;
    int b00 = (x0 << 14) + (y0 << 7);
    int b01 = (x0 << 14) + (y1 << 7);
    int b10 = (x1 << 14) + (y0 << 7);
    int b11 = (x1 << 14) + (y1 << 7);

    float v000 = ch[b00 + z0], v001 = ch[b00 + z1];
    float v010 = ch[b01 + z0], v011 = ch[b01 + z1];
    float v100 = ch[b10 + z0], v101 = ch[b10 + z1];
    float v110 = ch[b11 + z0], v111 = ch[b11 + z1];

    float c00 = v000 * (1.0f - wz) + v001 * wz;
    float c01 = v010 * (1.0f - wz) + v011 * wz;
    float c10 = v100 * (1.0f - wz) + v101 * wz;
    float c11 = v110 * (1.0f - wz) + v111 * wz;

    float val = (c00 * (1.0f - wy) + c01 * wy) * (1.0f - wx)
              + (c10 * (1.0f - wy) + c11 * wy) * wx;

    g_X0[v * 32 + 3 + c] = val;
}

// ---------------- fused edge_conv layer ----------------
// 8 warps/block; each warp: aggregate 8 vertices -> smem stage -> register-tiled
// dual-GEMM with f32x2 packed FMAs. Weights transposed in smem, row stride
// DINP+4 (== 4 mod 32 -> conflict-free 16B lane loads).
template<int DINP, int DOUT, bool RELU>
__global__ void __launch_bounds__(256)
k_layer(const float* __restrict__ X, float* __restrict__ Y,
        const float* __restrict__ Wsg, const float* __restrict__ Wng,
        const float* __restrict__ Bg, int din_real)
{
    constexpr int RSF = DINP + 4;       // weight row stride (floats)
    constexpr int NQ  = DOUT / 32;      // output cols per lane

    __shared__ __align__(16) float Ws[DOUT * RSF];
    __shared__ __align__(16) float Wn[DOUT * RSF];
    __shared__ __align__(16) float stg[8][16][DINP];  // [warp][0-7 self, 8-15 nb][i]
    __shared__ float Bs[DOUT];

    int t = threadIdx.x;
    // transpose-fill weights (zero-pad rows i >= din_real)
    for (int idx = t; idx < DOUT * DINP; idx += 256) {
        int j = idx / DINP, i = idx % DINP;
        float vs = 0.0f, vn = 0.0f;
        if (i < din_real) { vs = Wsg[i * DOUT + j]; vn = Wng[i * DOUT + j]; }
        Ws[j * RSF + i] = vs;
        Wn[j * RSF + i] = vn;
    }
    if (t < DOUT) Bs[t] = Bg[t];
    __syncthreads();

    int warp = t >> 5;
    int lane = t & 31;

    ull bias[NQ];
#pragma unroll
    for (int q = 0; q < NQ; q++) bias[q] = pack2(Bs[q * 32 + lane], 0.0f);

    for (int vbase = (blockIdx.x * 8 + warp) * 8; vbase < NV; vbase += gridDim.x * 64) {
        int vend = min(vbase + 8, NV) - vbase;

        // ---- aggregation: 8 vertices sequentially ----
        for (int m = 0; m < vend; m++) {
            int v = vbase + m;
            int o = g_off[v], d = g_deg[v], k = 0;
            float idg = g_invdeg[v];
            if (DINP == 64) {
                float2 xv = *(const float2*)&X[v * 64 + 2 * lane];
                float2 nb = make_float2(0.0f, 0.0f);
                for (; k + 4 <= d; k += 4) {
                    int s0 = g_csr[o + k],     s1 = g_csr[o + k + 1];
                    int s2 = g_csr[o + k + 2], s3 = g_csr[o + k + 3];
                    float2 a = *(const float2*)&X[s0 * 64 + 2 * lane];
                    float2 b = *(const float2*)&X[s1 * 64 + 2 * lane];
                    float2 c = *(const float2*)&X[s2 * 64 + 2 * lane];
                    float2 e = *(const float2*)&X[s3 * 64 + 2 * lane];
                    nb.x += a.x + b.x + c.x + e.x;
                    nb.y += a.y + b.y + c.y + e.y;
                }
                for (; k < d; k++) {
                    int s = g_csr[o + k];
                    float2 a = *(const float2*)&X[s * 64 + 2 * lane];
                    nb.x += a.x; nb.y += a.y;
                }
                nb.x *= idg; nb.y *= idg;
                *(float2*)&stg[warp][m][2 * lane]     = xv;
                *(float2*)&stg[warp][8 + m][2 * lane] = nb;
            } else {
                float xv = X[v * DINP + lane];
                float nb = 0.0f;
                for (; k + 4 <= d; k += 4) {
                    int s0 = g_csr[o + k],     s1 = g_csr[o + k + 1];
                    int s2 = g_csr[o + k + 2], s3 = g_csr[o + k + 3];
                    nb += X[s0 * DINP + lane] + X[s1 * DINP + lane]
                        + X[s2 * DINP + lane] + X[s3 * DINP + lane];
                }
                for (; k < d; k++) nb += X[g_csr[o + k] * DINP + lane];
                stg[warp][m][lane]     = xv;
                stg[warp][8 + m][lane] = nb * idg;
            }
        }
        __syncwarp();

        // ---- register-tiled dual GEMM (8 vertices x NQ outputs/lane) ----
        ull acc[NQ][8];
#pragma unroll
        for (int q = 0; q < NQ; q++)
#pragma unroll
            for (int m = 0; m < 8; m++) acc[q][m] = bias[q];

#pragma unroll 2
        for (int i0 = 0; i0 < DINP; i0 += 4) {
            ulonglong2 ws[NQ], wn[NQ];
#pragma unroll
            for (int q = 0; q < NQ; q++) {
                ws[q] = *(const ulonglong2*)&Ws[(q * 32 + lane) * RSF + i0];
                wn[q] = *(const ulonglong2*)&Wn[(q * 32 + lane) * RSF + i0];
            }
#pragma unroll
            for (int m = 0; m < 8; m++) {
                ulonglong2 xs2 = *(const ulonglong2*)&stg[warp][m][i0];
                ulonglong2 ns2 = *(const ulonglong2*)&stg[warp][8 + m][i0];
#pragma unroll
                for (int q = 0; q < NQ; q++) {
                    acc[q][m] = fma2(xs2.x, ws[q].x, acc[q][m]);
                    acc[q][m] = fma2(xs2.y, ws[q].y, acc[q][m]);
                    acc[q][m] = fma2(ns2.x, wn[q].x, acc[q][m]);
                    acc[q][m] = fma2(ns2.y, wn[q].y, acc[q][m]);
                }
            }
        }

        // ---- store ----
        for (int m = 0; m < vend; m++) {
            int v = vbase + m;
#pragma unroll
            for (int q = 0; q < NQ; q++) {
                float2 u = unpack2(acc[q][m]);
                float y = u.x + u.y;
                if (RELU) y = fmaxf(y, 0.3f * y);
                Y[v * DOUT + q * 32 + lane] = y;
            }
        }
        __syncwarp();
    }
}

// ---------------- final layer (64 -> 3): register weights + shfl reduce ----------------
__global__ void __launch_bounds__(256)
k_final(const float* __restrict__ X, float* __restrict__ out,
        const float* __restrict__ Wsg, const float* __restrict__ Wng,
        const float* __restrict__ Bg, const float* __restrict__ verts)
{
    int t = threadIdx.x;
    int warp = t >> 5, lane = t & 31;

    // per-lane weights: rows 2*lane, 2*lane+1 of [64,3] matrices
    float ws[2][3], wn[2][3];
#pragma unroll
    for (int e = 0; e < 2; e++)
#pragma unroll
        for (int c = 0; c < 3; c++) {
            ws[e][c] = Wsg[(2 * lane + e) * 3 + c];
            wn[e][c] = Wng[(2 * lane + e) * 3 + c];
        }
    float b3 = (lane < 3) ? Bg[lane] : 0.0f;

    for (int v = blockIdx.x * 8 + warp; v < NV; v += gridDim.x * 8) {
        float2 xv = *(const float2*)&X[v * 64 + 2 * lane];
        float2 nb = make_float2(0.0f, 0.0f);
        int o = g_off[v], d = g_deg[v], k = 0;
        for (; k + 4 <= d; k += 4) {
            int s0 = g_csr[o + k],     s1 = g_csr[o + k + 1];
            int s2 = g_csr[o + k + 2], s3 = g_csr[o + k + 3];
            float2 a = *(const float2*)&X[s0 * 64 + 2 * lane];
            float2 b = *(const float2*)&X[s1 * 64 + 2 * lane];
            float2 c = *(const float2*)&X[s2 * 64 + 2 * lane];
            float2 e = *(const float2*)&X[s3 * 64 + 2 * lane];
            nb.x += a.x + b.x + c.x + e.x;
            nb.y += a.y + b.y + c.y + e.y;
        }
        for (; k < d; k++) {
            int s = g_csr[o + k];
            float2 a = *(const float2*)&X[s * 64 + 2 * lane];
            nb.x += a.x; nb.y += a.y;
        }
        float idg = g_invdeg[v];
        nb.x *= idg; nb.y *= idg;

        float acc[3];
#pragma unroll
        for (int c = 0; c < 3; c++)
            acc[c] = xv.x * ws[0][c] + xv.y * ws[1][c]
                   + nb.x * wn[0][c] + nb.y * wn[1][c];

#pragma unroll
        for (int off = 16; off > 0; off >>= 1) {
#pragma unroll
            for (int c = 0; c < 3; c++)
                acc[c] += __shfl_xor_sync(0xFFFFFFFFu, acc[c], off);
        }
        if (lane < 3)
            out[v * 3 + lane] = verts[v * 3 + lane] + 0.1f * (acc[lane] + b3);
    }
}

// ---------------- launch ----------------
extern "C" void kernel_launch(void* const* d_in, const int* in_sizes, int n_in,
                              void* d_out, int out_size)
{
    const float* img   = (const float*)d_in[0];
    const float* verts = (const float*)d_in[1];
    const int*   esrc  = (const int*)d_in[2];
    const int*   edst  = (const int*)d_in[3];
    const float* ws0 = (const float*)d_in[4];
    const float* wn0 = (const float*)d_in[5];
    const float* b0  = (const float*)d_in[6];
    const float* ws1 = (const float*)d_in[7];
    const float* wn1 = (const float*)d_in[8];
    const float* b1  = (const float*)d_in[9];
    const float* ws2 = (const float*)d_in[10];
    const float* wn2 = (const float*)d_in[11];
    const float* b2  = (const float*)d_in[12];
    const float* ws3 = (const float*)d_in[13];
    const float* wn3 = (const float*)d_in[14];
    const float* b3  = (const float*)d_in[15];
    float* out = (float*)d_out;

    float *x0p, *x1p, *x2p, *x3p;
    cudaGetSymbolAddress((void**)&x0p, g_X0);
    cudaGetSymbolAddress((void**)&x1p, g_X1);
    cudaGetSymbolAddress((void**)&x2p, g_X2);
    cudaGetSymbolAddress((void**)&x3p, g_X3);

    const int TB = 256;
    const int GV = (NV + TB - 1) / TB;
    const int GE = (NE + TB - 1) / TB;
    const int GL = 1563;   // 12504 warps >= 12500 vertex tiles of 8

    // CSR build
    k_zero_deg<<<GV, TB>>>();
    k_deg<<<GE, TB>>>(edst);
    k_scan1<<<NBLK1, 1024>>>();
    k_scan2<<<1, 128>>>();
    k_scan3<<<GV, TB>>>();
    k_scatter<<<GE, TB>>>(esrc, edst);

    // features
    k_sample<<<(NV * 16 + TB - 1) / TB, TB>>>(img, verts);

    // layers: 19(->32pad)->32 -> 64 -> 64 -> 3
    k_layer<32, 32, true><<<GL, TB>>>(x0p, x1p, ws0, wn0, b0, 19);
    k_layer<32, 64, true><<<GL, TB>>>(x1p, x2p, ws1, wn1, b1, 32);
    k_layer<64, 64, true><<<GL, TB>>>(x2p, x3p, ws2, wn2, b2, 64);
    k_final<<<GL, TB>>>(x3p, out, ws3, wn3, b3, verts);
}

// round 3
// speedup vs baseline: 1.2262x; 1.0735x over previous
#include <cuda_runtime.h>

typedef unsigned long long ull;

#define NV      100000
#define NE      1600000
#define GRIDW   128
#define G3      (GRIDW*GRIDW*GRIDW)
#define NBLK1   ((NV + 1023) / 1024)

// ---------------- device scratch ----------------
__device__ int   g_deg[NV];
__device__ int   g_off[NV];
__device__ int   g_cursor[NV];
__device__ int   g_csr[NE];
__device__ float g_invdeg[NV];
__device__ int   g_bsum[128];
__device__ int   g_bbase[128];

__device__ float g_X0[NV * 32];
__device__ float g_X1[NV * 32];
__device__ float g_X2[NV * 64];
__device__ float g_X3[NV * 64];

// ---------------- f32x2 helpers ----------------
__device__ __forceinline__ ull pack2(float lo, float hi) {
    ull r; asm("mov.b64 %0, {%1,%2};" : "=l"(r) : "f"(lo), "f"(hi)); return r;
}
__device__ __forceinline__ float2 unpack2(ull v) {
    float2 f; asm("mov.b64 {%0,%1}, %2;" : "=f"(f.x), "=f"(f.y) : "l"(v)); return f;
}
__device__ __forceinline__ ull fma2(ull a, ull b, ull c) {
    ull d; asm("fma.rn.f32x2 %0, %1, %2, %3;" : "=l"(d) : "l"(a), "l"(b), "l"(c)); return d;
}

// ---------------- CSR build ----------------
__global__ void k_deg(const int* __restrict__ dst) {
    int e = blockIdx.x * blockDim.x + threadIdx.x;
    if (e < NE) atomicAdd(&g_deg[dst[e]], 1);
}

__global__ void k_scan1() {
    __shared__ int s[1024];
    int t = threadIdx.x;
    int i = blockIdx.x * 1024 + t;
    int v = (i < NV) ? g_deg[i] : 0;
    s[t] = v;
    __syncthreads();
    for (int d = 1; d < 1024; d <<= 1) {
        int a = (t >= d) ? s[t - d] : 0;
        __syncthreads();
        s[t] += a;
        __syncthreads();
    }
    if (i < NV) g_off[i] = s[t] - v;
    if (t == 1023) g_bsum[blockIdx.x] = s[1023];
}

__global__ void k_scan2() {
    __shared__ int s[128];
    int t = threadIdx.x;
    int v = (t < NBLK1) ? g_bsum[t] : 0;
    s[t] = v;
    __syncthreads();
    for (int d = 1; d < 128; d <<= 1) {
        int a = (t >= d) ? s[t - d] : 0;
        __syncthreads();
        s[t] += a;
        __syncthreads();
    }
    g_bbase[t] = s[t] - v;
}

__global__ void k_scan3() {
    int i = blockIdx.x * blockDim.x + threadIdx.x;
    if (i < NV) {
        int o = g_off[i] + g_bbase[i >> 10];
        g_off[i] = o;
        g_cursor[i] = o;
        int d = g_deg[i];
        g_invdeg[i] = 1.0f / fmaxf((float)d, 1.0f);
    }
}

__global__ void k_scatter(const int* __restrict__ src, const int* __restrict__ dst) {
    int e = blockIdx.x * blockDim.x + threadIdx.x;
    if (e < NE) {
        int p = atomicAdd(&g_cursor[dst[e]], 1);
        g_csr[p] = src[e];
    }
}

// ---------------- trilinear sampling (+ deg zeroing fused) ----------------
__global__ void k_sample(const float* __restrict__ img, const float* __restrict__ verts) {
    int tid = blockIdx.x * blockDim.x + threadIdx.x;
    if (tid >= NV * 16) return;
    int v = tid >> 4;
    int c = tid & 15;

    if (c == 0) g_deg[v] = 0;   // fused degree zeroing

    float px = verts[v * 3 + 0];
    float py = verts[v * 3 + 1];
    float pz = verts[v * 3 + 2];

    if (c < 3) {
        float coord = (c == 0) ? px : (c == 1 ? py : pz);
        g_X0[v * 32 + c] = coord * (1.0f / (float)GRIDW);
    }
    if (c < 13) g_X0[v * 32 + 19 + c] = 0.0f;

    float cx = fminf(fmaxf(px, 0.0f), 127.0f);
    float cy = fminf(fmaxf(py, 0.0f), 127.0f);
    float cz = fminf(fmaxf(pz, 0.0f), 127.0f);
    float fx0 = floorf(cx), fy0 = floorf(cy), fz0 = floorf(cz);
    int x0 = (int)fx0, y0 = (int)fy0, z0 = (int)fz0;
    int x1 = min(x0 + 1, 127), y1 = min(y0 + 1, 127), z1 = min(z0 + 1, 127);
    float wx = cx - fx0, wy = cy - fy0, wz = cz - fz0;

    const float* ch = img + (size_t)c * G3;
    int b00 = (x0 << 14) + (y0 << 7);
    int b01 = (x0 << 14) + (y1 << 7);
    int b10 = (x1 << 14) + (y0 << 7);
    int b11 = (x1 << 14) + (y1 << 7);

    float v000 = ch[b00 + z0], v001 = ch[b00 + z1];
    float v010 = ch[b01 + z0], v011 = ch[b01 + z1];
    float v100 = ch[b10 + z0], v101 = ch[b10 + z1];
    float v110 = ch[b11 + z0], v111 = ch[b11 + z1];

    float c00 = v000 * (1.0f - wz) + v001 * wz;
    float c01 = v010 * (1.0f - wz) + v011 * wz;
    float c10 = v100 * (1.0f - wz) + v101 * wz;
    float c11 = v110 * (1.0f - wz) + v111 * wz;

    float val = (c00 * (1.0f - wy) + c01 * wy) * (1.0f - wx)
              + (c10 * (1.0f - wy) + c11 * wy) * wx;

    g_X0[v * 32 + 3 + c] = val;
}

// ---------------- fused edge_conv layer ----------------
// 8 warps/block, 8 vertices per warp-tile.
// Aggregation: half-warp vector row loads (2 neighbors per LDG) + 2-vertex
// interleaved chains. GEMM: register-tiled dual GEMM with f32x2 FMAs.
template<int DINP, int DOUT, bool RELU>
__global__ void __launch_bounds__(256, 2)
k_layer(const float* __restrict__ X, float* __restrict__ Y,
        const float* __restrict__ Wsg, const float* __restrict__ Wng,
        const float* __restrict__ Bg, int din_real)
{
    constexpr int RSF = DINP + 4;
    constexpr int NQ  = DOUT / 32;

    __shared__ __align__(16) float Ws[DOUT * RSF];
    __shared__ __align__(16) float Wn[DOUT * RSF];
    __shared__ __align__(16) float stg[8][16][DINP];
    __shared__ float Bs[DOUT];

    int t = threadIdx.x;
    for (int idx = t; idx < DOUT * DINP; idx += 256) {
        int j = idx / DINP, i = idx % DINP;
        float vs = 0.0f, vn = 0.0f;
        if (i < din_real) { vs = Wsg[i * DOUT + j]; vn = Wng[i * DOUT + j]; }
        Ws[j * RSF + i] = vs;
        Wn[j * RSF + i] = vn;
    }
    if (t < DOUT) Bs[t] = Bg[t];
    __syncthreads();

    int warp = t >> 5;
    int lane = t & 31;
    int half = lane >> 4;          // 0/1: which neighbor of a pair this lane loads

    ull bias[NQ];
#pragma unroll
    for (int q = 0; q < NQ; q++) bias[q] = pack2(Bs[q * 32 + lane], 0.0f);

    for (int vbase = (blockIdx.x * 8 + warp) * 8; vbase < NV; vbase += gridDim.x * 64) {
        int vend = min(vbase + 8, NV) - vbase;

        // ---- aggregation: interleaved vertex pairs ----
        for (int m = 0; m < vend; m += 2) {
            int vA = vbase + m;
            bool hasB = (m + 1) < vend;
            int vB = hasB ? vA + 1 : vA;

            int oA = g_off[vA], dA = g_deg[vA];
            int oB = g_off[vB], dB = hasB ? g_deg[vB] : 0;
            int dmax = max(dA, dB);

            if (DINP == 64) {
                // self rows (full-warp float2)
                float2 xa = *(const float2*)&X[(size_t)vA * 64 + 2 * lane];
                *(float2*)&stg[warp][m][2 * lane] = xa;
                if (hasB) {
                    float2 xb = *(const float2*)&X[(size_t)vB * 64 + 2 * lane];
                    *(float2*)&stg[warp][m + 1][2 * lane] = xb;
                }
                int col = (lane & 15) * 4;
                float4 nA = make_float4(0, 0, 0, 0);
                float4 nB = make_float4(0, 0, 0, 0);
                for (int k = 0; k < dmax; k += 4) {
#pragma unroll
                    for (int j = 0; j < 4; j += 2) {
                        int ii = k + j + half;
                        bool pA = ii < dA, pB = ii < dB;
                        int sA = 0, sB = 0;
                        if (pA) sA = g_csr[oA + ii];
                        if (pB) sB = g_csr[oB + ii];
                        float4 fA = make_float4(0, 0, 0, 0);
                        float4 fB = make_float4(0, 0, 0, 0);
                        if (pA) fA = *(const float4*)&X[(size_t)sA * 64 + col];
                        if (pB) fB = *(const float4*)&X[(size_t)sB * 64 + col];
                        nA.x += fA.x; nA.y += fA.y; nA.z += fA.z; nA.w += fA.w;
                        nB.x += fB.x; nB.y += fB.y; nB.z += fB.z; nB.w += fB.w;
                    }
                }
                nA.x += __shfl_xor_sync(0xFFFFFFFFu, nA.x, 16);
                nA.y += __shfl_xor_sync(0xFFFFFFFFu, nA.y, 16);
                nA.z += __shfl_xor_sync(0xFFFFFFFFu, nA.z, 16);
                nA.w += __shfl_xor_sync(0xFFFFFFFFu, nA.w, 16);
                float ia = g_invdeg[vA];
                nA.x *= ia; nA.y *= ia; nA.z *= ia; nA.w *= ia;
                if (half == 0) *(float4*)&stg[warp][8 + m][col] = nA;
                if (hasB) {
                    nB.x += __shfl_xor_sync(0xFFFFFFFFu, nB.x, 16);
                    nB.y += __shfl_xor_sync(0xFFFFFFFFu, nB.y, 16);
                    nB.z += __shfl_xor_sync(0xFFFFFFFFu, nB.z, 16);
                    nB.w += __shfl_xor_sync(0xFFFFFFFFu, nB.w, 16);
                    float ib = g_invdeg[vB];
                    nB.x *= ib; nB.y *= ib; nB.z *= ib; nB.w *= ib;
                    if (half == 0) *(float4*)&stg[warp][8 + m + 1][col] = nB;
                }
            } else {
                // DINP == 32
                float xa = X[(size_t)vA * 32 + lane];
                stg[warp][m][lane] = xa;
                if (hasB) {
                    float xb = X[(size_t)vB * 32 + lane];
                    stg[warp][m + 1][lane] = xb;
                }
                int col = (lane & 15) * 2;
                float2 nA = make_float2(0, 0);
                float2 nB = make_float2(0, 0);
                for (int k = 0; k < dmax; k += 4) {
#pragma unroll
                    for (int j = 0; j < 4; j += 2) {
                        int ii = k + j + half;
                        bool pA = ii < dA, pB = ii < dB;
                        int sA = 0, sB = 0;
                        if (pA) sA = g_csr[oA + ii];
                        if (pB) sB = g_csr[oB + ii];
                        float2 fA = make_float2(0, 0);
                        float2 fB = make_float2(0, 0);
                        if (pA) fA = *(const float2*)&X[(size_t)sA * 32 + col];
                        if (pB) fB = *(const float2*)&X[(size_t)sB * 32 + col];
                        nA.x += fA.x; nA.y += fA.y;
                        nB.x += fB.x; nB.y += fB.y;
                    }
                }
                nA.x += __shfl_xor_sync(0xFFFFFFFFu, nA.x, 16);
                nA.y += __shfl_xor_sync(0xFFFFFFFFu, nA.y, 16);
                float ia = g_invdeg[vA];
                nA.x *= ia; nA.y *= ia;
                if (half == 0) *(float2*)&stg[warp][8 + m][col] = nA;
                if (hasB) {
                    nB.x += __shfl_xor_sync(0xFFFFFFFFu, nB.x, 16);
                    nB.y += __shfl_xor_sync(0xFFFFFFFFu, nB.y, 16);
                    float ib = g_invdeg[vB];
                    nB.x *= ib; nB.y *= ib;
                    if (half == 0) *(float2*)&stg[warp][8 + m + 1][col] = nB;
                }
            }
        }
        __syncwarp();

        // ---- register-tiled dual GEMM ----
        ull acc[NQ][8];
#pragma unroll
        for (int q = 0; q < NQ; q++)
#pragma unroll
            for (int m = 0; m < 8; m++) acc[q][m] = bias[q];

#pragma unroll 2
        for (int i0 = 0; i0 < DINP; i0 += 4) {
            ulonglong2 ws[NQ], wn[NQ];
#pragma unroll
            for (int q = 0; q < NQ; q++) {
                ws[q] = *(const ulonglong2*)&Ws[(q * 32 + lane) * RSF + i0];
                wn[q] = *(const ulonglong2*)&Wn[(q * 32 + lane) * RSF + i0];
            }
#pragma unroll
            for (int m = 0; m < 8; m++) {
                ulonglong2 xs2 = *(const ulonglong2*)&stg[warp][m][i0];
                ulonglong2 ns2 = *(const ulonglong2*)&stg[warp][8 + m][i0];
#pragma unroll
                for (int q = 0; q < NQ; q++) {
                    acc[q][m] = fma2(xs2.x, ws[q].x, acc[q][m]);
                    acc[q][m] = fma2(xs2.y, ws[q].y, acc[q][m]);
                    acc[q][m] = fma2(ns2.x, wn[q].x, acc[q][m]);
                    acc[q][m] = fma2(ns2.y, wn[q].y, acc[q][m]);
                }
            }
        }

        // ---- store ----
        for (int m = 0; m < vend; m++) {
            int v = vbase + m;
#pragma unroll
            for (int q = 0; q < NQ; q++) {
                float2 u = unpack2(acc[q][m]);
                float y = u.x + u.y;
                if (RELU) y = fmaxf(y, 0.3f * y);
                Y[(size_t)v * DOUT + q * 32 + lane] = y;
            }
        }
        __syncwarp();
    }
}

// ---------------- final layer (64 -> 3) ----------------
__global__ void __launch_bounds__(256)
k_final(const float* __restrict__ X, float* __restrict__ out,
        const float* __restrict__ Wsg, const float* __restrict__ Wng,
        const float* __restrict__ Bg, const float* __restrict__ verts)
{
    int t = threadIdx.x;
    int warp = t >> 5, lane = t & 31;

    float ws[2][3], wn[2][3];
#pragma unroll
    for (int e = 0; e < 2; e++)
#pragma unroll
        for (int c = 0; c < 3; c++) {
            ws[e][c] = Wsg[(2 * lane + e) * 3 + c];
            wn[e][c] = Wng[(2 * lane + e) * 3 + c];
        }
    float b3 = (lane < 3) ? Bg[lane] : 0.0f;

    int v = blockIdx.x * 8 + warp;
    if (v >= NV) return;

    float2 xv = *(const float2*)&X[(size_t)v * 64 + 2 * lane];
    float2 nb = make_float2(0.0f, 0.0f);
    int o = g_off[v], d = g_deg[v], k = 0;
    for (; k + 4 <= d; k += 4) {
        int s0 = g_csr[o + k],     s1 = g_csr[o + k + 1];
        int s2 = g_csr[o + k + 2], s3 = g_csr[o + k + 3];
        float2 a = *(const float2*)&X[(size_t)s0 * 64 + 2 * lane];
        float2 b = *(const float2*)&X[(size_t)s1 * 64 + 2 * lane];
        float2 c = *(const float2*)&X[(size_t)s2 * 64 + 2 * lane];
        float2 e = *(const float2*)&X[(size_t)s3 * 64 + 2 * lane];
        nb.x += a.x + b.x + c.x + e.x;
        nb.y += a.y + b.y + c.y + e.y;
    }
    for (; k < d; k++) {
        int s = g_csr[o + k];
        float2 a = *(const float2*)&X[(size_t)s * 64 + 2 * lane];
        nb.x += a.x; nb.y += a.y;
    }
    float idg = g_invdeg[v];
    nb.x *= idg; nb.y *= idg;

    float acc[3];
#pragma unroll
    for (int c = 0; c < 3; c++)
        acc[c] = xv.x * ws[0][c] + xv.y * ws[1][c]
               + nb.x * wn[0][c] + nb.y * wn[1][c];

#pragma unroll
    for (int off = 16; off > 0; off >>= 1) {
#pragma unroll
        for (int c = 0; c < 3; c++)
            acc[c] += __shfl_xor_sync(0xFFFFFFFFu, acc[c], off);
    }
    if (lane < 3)
        out[v * 3 + lane] = verts[v * 3 + lane] + 0.1f * (acc[lane] + b3);
}

// ---------------- launch ----------------
extern "C" void kernel_launch(void* const* d_in, const int* in_sizes, int n_in,
                              void* d_out, int out_size)
{
    const float* img   = (const float*)d_in[0];
    const float* verts = (const float*)d_in[1];
    const int*   esrc  = (const int*)d_in[2];
    const int*   edst  = (const int*)d_in[3];
    const float* ws0 = (const float*)d_in[4];
    const float* wn0 = (const float*)d_in[5];
    const float* b0  = (const float*)d_in[6];
    const float* ws1 = (const float*)d_in[7];
    const float* wn1 = (const float*)d_in[8];
    const float* b1  = (const float*)d_in[9];
    const float* ws2 = (const float*)d_in[10];
    const float* wn2 = (const float*)d_in[11];
    const float* b2  = (const float*)d_in[12];
    const float* ws3 = (const float*)d_in[13];
    const float* wn3 = (const float*)d_in[14];
    const float* b3  = (const float*)d_in[15];
    float* out = (float*)d_out;

    float *x0p, *x1p, *x2p, *x3p;
    cudaGetSymbolAddress((void**)&x0p, g_X0);
    cudaGetSymbolAddress((void**)&x1p, g_X1);
    cudaGetSymbolAddress((void**)&x2p, g_X2);
    cudaGetSymbolAddress((void**)&x3p, g_X3);

    const int TB = 256;
    const int GV = (NV + TB - 1) / TB;
    const int GE = (NE + TB - 1) / TB;
    const int GL = 1563;

    // sample (also zeroes g_deg) first, then CSR build
    k_sample<<<(NV * 16 + TB - 1) / TB, TB>>>(img, verts);
    k_deg<<<GE, TB>>>(edst);
    k_scan1<<<NBLK1, 1024>>>();
    k_scan2<<<1, 128>>>();
    k_scan3<<<GV, TB>>>();
    k_scatter<<<GE, TB>>>(esrc, edst);

    // layers
    k_layer<32, 32, true><<<GL, TB>>>(x0p, x1p, ws0, wn0, b0, 19);
    k_layer<32, 64, true><<<GL, TB>>>(x1p, x2p, ws1, wn1, b1, 32);
    k_layer<64, 64, true><<<GL, TB>>>(x2p, x3p, ws2, wn2, b2, 64);
    k_final<<<(NV + 7) / 8, TB>>>(x3p, out, ws3, wn3, b3, verts);
}

// round 4
// speedup vs baseline: 1.2447x; 1.0150x over previous
#include <cuda_runtime.h>

typedef unsigned long long ull;

#define NV      100000
#define NE      1600000
#define GRIDW   128
#define G3      (GRIDW*GRIDW*GRIDW)
#define BCAP    128          // neighbor bucket capacity per vertex

// ---------------- device scratch ----------------
__device__ int   g_cursor[NV];
__device__ int   g_csr[NV * BCAP];

__device__ float g_X0[NV * 32];
__device__ float g_X1[NV * 32];
__device__ float g_X2[NV * 64];
__device__ float g_X3[NV * 64];
__device__ float4 g_P[NV];    // h3 @ Wn3
__device__ float4 g_S[NV];    // h3 @ Ws3 + b3

// ---------------- f32x2 helpers ----------------
__device__ __forceinline__ ull pack2(float lo, float hi) {
    ull r; asm("mov.b64 %0, {%1,%2};" : "=l"(r) : "f"(lo), "f"(hi)); return r;
}
__device__ __forceinline__ float2 unpack2(ull v) {
    float2 f; asm("mov.b64 {%0,%1}, %2;" : "=f"(f.x), "=f"(f.y) : "l"(v)); return f;
}
__device__ __forceinline__ ull fma2(ull a, ull b, ull c) {
    ull d; asm("fma.rn.f32x2 %0, %1, %2, %3;" : "=l"(d) : "l"(a), "l"(b), "l"(c)); return d;
}

// ---------------- bucket scatter (replaces deg+scan+scatter) ----------------
__global__ void k_scatter(const int4* __restrict__ src4, const int4* __restrict__ dst4) {
    int e = blockIdx.x * blockDim.x + threadIdx.x;
    if (e < NE / 4) {
        int4 s = src4[e];
        int4 d = dst4[e];
        int p;
        p = atomicAdd(&g_cursor[d.x], 1); g_csr[d.x * BCAP + p] = s.x;
        p = atomicAdd(&g_cursor[d.y], 1); g_csr[d.y * BCAP + p] = s.y;
        p = atomicAdd(&g_cursor[d.z], 1); g_csr[d.z * BCAP + p] = s.z;
        p = atomicAdd(&g_cursor[d.w], 1); g_csr[d.w * BCAP + p] = s.w;
    }
}

// ---------------- trilinear sampling (+ cursor zeroing fused) ----------------
__global__ void k_sample(const float* __restrict__ img, const float* __restrict__ verts) {
    int tid = blockIdx.x * blockDim.x + threadIdx.x;
    if (tid >= NV * 16) return;
    int v = tid >> 4;
    int c = tid & 15;

    if (c == 0) g_cursor[v] = 0;   // fused cursor zeroing

    float px = verts[v * 3 + 0];
    float py = verts[v * 3 + 1];
    float pz = verts[v * 3 + 2];

    if (c < 3) {
        float coord = (c == 0) ? px : (c == 1 ? py : pz);
        g_X0[v * 32 + c] = coord * (1.0f / (float)GRIDW);
    }
    if (c < 13) g_X0[v * 32 + 19 + c] = 0.0f;

    float cx = fminf(fmaxf(px, 0.0f), 127.0f);
    float cy = fminf(fmaxf(py, 0.0f), 127.0f);
    float cz = fminf(fmaxf(pz, 0.0f), 127.0f);
    float fx0 = floorf(cx), fy0 = floorf(cy), fz0 = floorf(cz);
    int x0 = (int)fx0, y0 = (int)fy0, z0 = (int)fz0;
    int x1 = min(x0 + 1, 127), y1 = min(y0 + 1, 127), z1 = min(z0 + 1, 127);
    float wx = cx - fx0, wy = cy - fy0, wz = cz - fz0;

    const float* ch = img + (size_t)c * G3;
    int b00 = (x0 << 14) + (y0 << 7);
    int b01 = (x0 << 14) + (y1 << 7);
    int b10 = (x1 << 14) + (y0 << 7);
    int b11 = (x1 << 14) + (y1 << 7);

    float v000 = ch[b00 + z0], v001 = ch[b00 + z1];
    float v010 = ch[b01 + z0], v011 = ch[b01 + z1];
    float v100 = ch[b10 + z0], v101 = ch[b10 + z1];
    float v110 = ch[b11 + z0], v111 = ch[b11 + z1];

    float c00 = v000 * (1.0f - wz) + v001 * wz;
    float c01 = v010 * (1.0f - wz) + v011 * wz;
    float c10 = v100 * (1.0f - wz) + v101 * wz;
    float c11 = v110 * (1.0f - wz) + v111 * wz;

    float val = (c00 * (1.0f - wy) + c01 * wy) * (1.0f - wx)
              + (c10 * (1.0f - wy) + c11 * wy) * wx;

    g_X0[v * 32 + 3 + c] = val;
}

// ---------------- fused edge_conv layer ----------------
template<int DINP, int DOUT, bool RELU>
__global__ void __launch_bounds__(256, 2)
k_layer(const float* __restrict__ X, float* __restrict__ Y,
        const float* __restrict__ Wsg, const float* __restrict__ Wng,
        const float* __restrict__ Bg, int din_real)
{
    constexpr int RSF = DINP + 4;
    constexpr int NQ  = DOUT / 32;

    __shared__ __align__(16) float Ws[DOUT * RSF];
    __shared__ __align__(16) float Wn[DOUT * RSF];
    __shared__ __align__(16) float stg[8][16][DINP];
    __shared__ float Bs[DOUT];

    int t = threadIdx.x;
    for (int idx = t; idx < DOUT * DINP; idx += 256) {
        int j = idx / DINP, i = idx % DINP;
        float vs = 0.0f, vn = 0.0f;
        if (i < din_real) { vs = Wsg[i * DOUT + j]; vn = Wng[i * DOUT + j]; }
        Ws[j * RSF + i] = vs;
        Wn[j * RSF + i] = vn;
    }
    if (t < DOUT) Bs[t] = Bg[t];
    __syncthreads();

    int warp = t >> 5;
    int lane = t & 31;
    int half = lane >> 4;

    ull bias[NQ];
#pragma unroll
    for (int q = 0; q < NQ; q++) bias[q] = pack2(Bs[q * 32 + lane], 0.0f);

    for (int vbase = (blockIdx.x * 8 + warp) * 8; vbase < NV; vbase += gridDim.x * 64) {
        int vend = min(vbase + 8, NV) - vbase;

        // ---- aggregation: interleaved vertex pairs ----
        for (int m = 0; m < vend; m += 2) {
            int vA = vbase + m;
            bool hasB = (m + 1) < vend;
            int vB = hasB ? vA + 1 : vA;

            int oA = vA * BCAP, dA = g_cursor[vA];
            int oB = vB * BCAP, dB = hasB ? g_cursor[vB] : 0;
            int dmax = max(dA, dB);

            if (DINP == 64) {
                float2 xa = *(const float2*)&X[(size_t)vA * 64 + 2 * lane];
                *(float2*)&stg[warp][m][2 * lane] = xa;
                if (hasB) {
                    float2 xb = *(const float2*)&X[(size_t)vB * 64 + 2 * lane];
                    *(float2*)&stg[warp][m + 1][2 * lane] = xb;
                }
                int col = (lane & 15) * 4;
                float4 nA = make_float4(0, 0, 0, 0);
                float4 nB = make_float4(0, 0, 0, 0);
                for (int k = 0; k < dmax; k += 4) {
#pragma unroll
                    for (int j = 0; j < 4; j += 2) {
                        int ii = k + j + half;
                        bool pA = ii < dA, pB = ii < dB;
                        int sA = 0, sB = 0;
                        if (pA) sA = g_csr[oA + ii];
                        if (pB) sB = g_csr[oB + ii];
                        float4 fA = make_float4(0, 0, 0, 0);
                        float4 fB = make_float4(0, 0, 0, 0);
                        if (pA) fA = *(const float4*)&X[(size_t)sA * 64 + col];
                        if (pB) fB = *(const float4*)&X[(size_t)sB * 64 + col];
                        nA.x += fA.x; nA.y += fA.y; nA.z += fA.z; nA.w += fA.w;
                        nB.x += fB.x; nB.y += fB.y; nB.z += fB.z; nB.w += fB.w;
                    }
                }
                nA.x += __shfl_xor_sync(0xFFFFFFFFu, nA.x, 16);
                nA.y += __shfl_xor_sync(0xFFFFFFFFu, nA.y, 16);
                nA.z += __shfl_xor_sync(0xFFFFFFFFu, nA.z, 16);
                nA.w += __shfl_xor_sync(0xFFFFFFFFu, nA.w, 16);
                float ia = 1.0f / fmaxf((float)dA, 1.0f);
                nA.x *= ia; nA.y *= ia; nA.z *= ia; nA.w *= ia;
                if (half == 0) *(float4*)&stg[warp][8 + m][col] = nA;
                if (hasB) {
                    nB.x += __shfl_xor_sync(0xFFFFFFFFu, nB.x, 16);
                    nB.y += __shfl_xor_sync(0xFFFFFFFFu, nB.y, 16);
                    nB.z += __shfl_xor_sync(0xFFFFFFFFu, nB.z, 16);
                    nB.w += __shfl_xor_sync(0xFFFFFFFFu, nB.w, 16);
                    float ib = 1.0f / fmaxf((float)dB, 1.0f);
                    nB.x *= ib; nB.y *= ib; nB.z *= ib; nB.w *= ib;
                    if (half == 0) *(float4*)&stg[warp][8 + m + 1][col] = nB;
                }
            } else {
                float xa = X[(size_t)vA * 32 + lane];
                stg[warp][m][lane] = xa;
                if (hasB) {
                    float xb = X[(size_t)vB * 32 + lane];
                    stg[warp][m + 1][lane] = xb;
                }
                int col = (lane & 15) * 2;
                float2 nA = make_float2(0, 0);
                float2 nB = make_float2(0, 0);
                for (int k = 0; k < dmax; k += 4) {
#pragma unroll
                    for (int j = 0; j < 4; j += 2) {
                        int ii = k + j + half;
                        bool pA = ii < dA, pB = ii < dB;
                        int sA = 0, sB = 0;
                        if (pA) sA = g_csr[oA + ii];
                        if (pB) sB = g_csr[oB + ii];
                        float2 fA = make_float2(0, 0);
                        float2 fB = make_float2(0, 0);
                        if (pA) fA = *(const float2*)&X[(size_t)sA * 32 + col];
                        if (pB) fB = *(const float2*)&X[(size_t)sB * 32 + col];
                        nA.x += fA.x; nA.y += fA.y;
                        nB.x += fB.x; nB.y += fB.y;
                    }
                }
                nA.x += __shfl_xor_sync(0xFFFFFFFFu, nA.x, 16);
                nA.y += __shfl_xor_sync(0xFFFFFFFFu, nA.y, 16);
                float ia = 1.0f / fmaxf((float)dA, 1.0f);
                nA.x *= ia; nA.y *= ia;
                if (half == 0) *(float2*)&stg[warp][8 + m][col] = nA;
                if (hasB) {
                    nB.x += __shfl_xor_sync(0xFFFFFFFFu, nB.x, 16);
                    nB.y += __shfl_xor_sync(0xFFFFFFFFu, nB.y, 16);
                    float ib = 1.0f / fmaxf((float)dB, 1.0f);
                    nB.x *= ib; nB.y *= ib;
                    if (half == 0) *(float2*)&stg[warp][8 + m + 1][col] = nB;
                }
            }
        }
        __syncwarp();

        // ---- register-tiled dual GEMM ----
        ull acc[NQ][8];
#pragma unroll
        for (int q = 0; q < NQ; q++)
#pragma unroll
            for (int m = 0; m < 8; m++) acc[q][m] = bias[q];

#pragma unroll 2
        for (int i0 = 0; i0 < DINP; i0 += 4) {
            ulonglong2 ws[NQ], wn[NQ];
#pragma unroll
            for (int q = 0; q < NQ; q++) {
                ws[q] = *(const ulonglong2*)&Ws[(q * 32 + lane) * RSF + i0];
                wn[q] = *(const ulonglong2*)&Wn[(q * 32 + lane) * RSF + i0];
            }
#pragma unroll
            for (int m = 0; m < 8; m++) {
                ulonglong2 xs2 = *(const ulonglong2*)&stg[warp][m][i0];
                ulonglong2 ns2 = *(const ulonglong2*)&stg[warp][8 + m][i0];
#pragma unroll
                for (int q = 0; q < NQ; q++) {
                    acc[q][m] = fma2(xs2.x, ws[q].x, acc[q][m]);
                    acc[q][m] = fma2(xs2.y, ws[q].y, acc[q][m]);
                    acc[q][m] = fma2(ns2.x, wn[q].x, acc[q][m]);
                    acc[q][m] = fma2(ns2.y, wn[q].y, acc[q][m]);
                }
            }
        }

        // ---- store ----
        for (int m = 0; m < vend; m++) {
            int v = vbase + m;
#pragma unroll
            for (int q = 0; q < NQ; q++) {
                float2 u = unpack2(acc[q][m]);
                float y = u.x + u.y;
                if (RELU) y = fmaxf(y, 0.3f * y);
                Y[(size_t)v * DOUT + q * 32 + lane] = y;
            }
        }
        __syncwarp();
    }
}

// ---------------- final layer, stage 1: project h3 by Ws3/Wn3 ----------------
__global__ void __launch_bounds__(256)
k_proj(const float* __restrict__ X,
       const float* __restrict__ Wsg, const float* __restrict__ Wng,
       const float* __restrict__ Bg)
{
    int t = threadIdx.x;
    int warp = t >> 5, lane = t & 31;

    float ws[2][3], wn[2][3];
#pragma unroll
    for (int e = 0; e < 2; e++)
#pragma unroll
        for (int c = 0; c < 3; c++) {
            ws[e][c] = Wsg[(2 * lane + e) * 3 + c];
            wn[e][c] = Wng[(2 * lane + e) * 3 + c];
        }

    int v = blockIdx.x * 8 + warp;
    if (v >= NV) return;

    float2 xv = *(const float2*)&X[(size_t)v * 64 + 2 * lane];

    float as[3], an[3];
#pragma unroll
    for (int c = 0; c < 3; c++) {
        as[c] = xv.x * ws[0][c] + xv.y * ws[1][c];
        an[c] = xv.x * wn[0][c] + xv.y * wn[1][c];
    }
#pragma unroll
    for (int off = 16; off > 0; off >>= 1) {
#pragma unroll
        for (int c = 0; c < 3; c++) {
            as[c] += __shfl_xor_sync(0xFFFFFFFFu, as[c], off);
            an[c] += __shfl_xor_sync(0xFFFFFFFFu, an[c], off);
        }
    }
    if (lane == 0) {
        g_S[v] = make_float4(as[0] + Bg[0], as[1] + Bg[1], as[2] + Bg[2], 0.0f);
        g_P[v] = make_float4(an[0], an[1], an[2], 0.0f);
    }
}

// ---------------- final layer, stage 2: 3-wide gather + output ----------------
__global__ void __launch_bounds__(256)
k_fin2(float* __restrict__ out, const float* __restrict__ verts)
{
    int v = blockIdx.x * blockDim.x + threadIdx.x;
    if (v >= NV) return;

    int d = g_cursor[v];
    int o = v * BCAP;
    float ax = 0.0f, ay = 0.0f, az = 0.0f;
    int k = 0;
    for (; k + 4 <= d; k += 4) {
        int s0 = g_csr[o + k],     s1 = g_csr[o + k + 1];
        int s2 = g_csr[o + k + 2], s3 = g_csr[o + k + 3];
        float4 p0 = g_P[s0], p1 = g_P[s1], p2 = g_P[s2], p3 = g_P[s3];
        ax += (p0.x + p1.x) + (p2.x + p3.x);
        ay += (p0.y + p1.y) + (p2.y + p3.y);
        az += (p0.z + p1.z) + (p2.z + p3.z);
    }
    for (; k < d; k++) {
        float4 p = g_P[g_csr[o + k]];
        ax += p.x; ay += p.y; az += p.z;
    }
    float idg = 1.0f / fmaxf((float)d, 1.0f);
    float4 S = g_S[v];
    out[v * 3 + 0] = verts[v * 3 + 0] + 0.1f * (S.x + idg * ax);
    out[v * 3 + 1] = verts[v * 3 + 1] + 0.1f * (S.y + idg * ay);
    out[v * 3 + 2] = verts[v * 3 + 2] + 0.1f * (S.z + idg * az);
}

// ---------------- launch ----------------
extern "C" void kernel_launch(void* const* d_in, const int* in_sizes, int n_in,
                              void* d_out, int out_size)
{
    const float* img   = (const float*)d_in[0];
    const float* verts = (const float*)d_in[1];
    const int*   esrc  = (const int*)d_in[2];
    const int*   edst  = (const int*)d_in[3];
    const float* ws0 = (const float*)d_in[4];
    const float* wn0 = (const float*)d_in[5];
    const float* b0  = (const float*)d_in[6];
    const float* ws1 = (const float*)d_in[7];
    const float* wn1 = (const float*)d_in[8];
    const float* b1  = (const float*)d_in[9];
    const float* ws2 = (const float*)d_in[10];
    const float* wn2 = (const float*)d_in[11];
    const float* b2  = (const float*)d_in[12];
    const float* ws3 = (const float*)d_in[13];
    const float* wn3 = (const float*)d_in[14];
    const float* b3  = (const float*)d_in[15];
    float* out = (float*)d_out;

    float *x0p, *x1p, *x2p, *x3p;
    cudaGetSymbolAddress((void**)&x0p, g_X0);
    cudaGetSymbolAddress((void**)&x1p, g_X1);
    cudaGetSymbolAddress((void**)&x2p, g_X2);
    cudaGetSymbolAddress((void**)&x3p, g_X3);

    const int TB = 256;
    const int GL = 1563;

    // sample (also zeroes cursors), then one-pass bucket scatter
    k_sample<<<(NV * 16 + TB - 1) / TB, TB>>>(img, verts);
    k_scatter<<<(NE / 4 + TB - 1) / TB, TB>>>((const int4*)esrc, (const int4*)edst);

    // layers
    k_layer<32, 32, true><<<GL, TB>>>(x0p, x1p, ws0, wn0, b0, 19);
    k_layer<32, 64, true><<<GL, TB>>>(x1p, x2p, ws1, wn1, b1, 32);
    k_layer<64, 64, true><<<GL, TB>>>(x2p, x3p, ws2, wn2, b2, 64);
    k_proj<<<(NV + 7) / 8, TB>>>(x3p, ws3, wn3, b3);
    k_fin2<<<(NV + TB - 1) / TB, TB>>>(out, verts);
}